// round 13
// baseline (speedup 1.0000x reference)
#include <cuda_runtime.h>

#define B_    4
#define C_    32
#define H_    128
#define W_    256
#define CR_   85
#define HW_   (H_*W_)        // 32768
#define CHW_  (C_*HW_)       // 1048576
#define WW_   (W_*W_)        // 65536
#define BHWW_ (B_*H_*WW_)    // 33554432
#define XN_   (B_*CHW_)      // 4194304
#define STR_  34             // padded row stride for smem q/k

typedef unsigned long long ull;

// Band tiles (d=0 frame: delta = it-jt in [0,3]) and off-band (copy) tiles.
__constant__ unsigned char CTILE[26] = {
    0, 9, 18, 27, 36, 45, 54, 63,
    8, 17, 26, 35, 44, 53, 62,
    16, 25, 34, 43, 52, 61,
    24, 33, 42, 51, 60
};
__constant__ unsigned char CPTILE[38] = {
    1, 2, 3, 4, 5, 6, 7,
    10, 11, 12, 13, 14, 15,
    19, 20, 21, 22, 23,
    28, 29, 30, 31,
    32, 37, 38, 39,
    40, 41, 46, 47,
    48, 49, 50, 55,
    56, 57, 58, 59
};
// copy warp w in [0,5): tiles [COFF[w], COFF[w+1]);  band warp bw in [0,3)
__constant__ unsigned char COFF[6] = {0, 8, 16, 24, 31, 38};
__constant__ unsigned char BOFF[4] = {0, 9, 18, 26};

// ---- packed f32x2 helpers (Blackwell sm_103a) ----
__device__ __forceinline__ ull pack2(float lo, float hi) {
    ull r;
    asm("mov.b64 %0, {%1, %2};" : "=l"(r) : "f"(lo), "f"(hi));
    return r;
}
__device__ __forceinline__ void fma2(ull &d, ull a, ull b) {
    asm("fma.rn.f32x2 %0, %1, %2, %0;" : "+l"(d) : "l"(a), "l"(b));
}
__device__ __forceinline__ ull add2(ull a, ull b) {
    ull r;
    asm("add.rn.f32x2 %0, %1, %2;" : "=l"(r) : "l"(a), "l"(b));
    return r;
}
__device__ __forceinline__ float sum2(ull a) {
    float lo, hi;
    asm("mov.b64 {%0, %1}, %2;" : "=f"(lo), "=f"(hi) : "l"(a));
    return lo + hi;
}

extern "C" __global__ void __launch_bounds__(256, 2)
pab_kernel(const float* __restrict__ x_left, const float* __restrict__ x_right,
           const float* __restrict__ cost,
           const float* __restrict__ qw, const float* __restrict__ qb,
           const float* __restrict__ qg, const float* __restrict__ qbe,
           const float* __restrict__ qm, const float* __restrict__ qv,
           const float* __restrict__ kw, const float* __restrict__ kb,
           const float* __restrict__ kg, const float* __restrict__ kbe,
           const float* __restrict__ km, const float* __restrict__ kv,
           float* __restrict__ out)
{
    extern __shared__ float sm[];
    float* qA  = sm;                    // [256][34]
    float* kA  = sm + 8704;             // [256][34]
    float* wqs = sm + 17408;            // [1024] -> band score staging after proj
    float* wks = wqs + 1024;            // [1024]
    float* bqs = wks + 1024;            // [32]
    float* bks = bqs + 32;              // [32]

    const int tid  = threadIdx.x;
    const int warp = tid >> 5;
    const int lane = tid & 31;
    const int bx   = blockIdx.x;
    const int d    = bx & 1;
    const int bh   = bx >> 1;
    const int b    = bh >> 7;
    const int h    = bh & 127;

    // ---- fold BatchNorm into conv weights/bias ----
    for (int t = tid; t < 1024; t += 256) {
        const int o = t >> 5;
        wqs[t] = qw[t] * (qg[o] * rsqrtf(qv[o] + 1e-5f));
        wks[t] = kw[t] * (kg[o] * rsqrtf(kv[o] + 1e-5f));
    }
    if (tid < 32) {
        const float sq = qg[tid] * rsqrtf(qv[tid] + 1e-5f);
        const float sk = kg[tid] * rsqrtf(kv[tid] + 1e-5f);
        bqs[tid] = qb[tid] * sq + qbe[tid] - qm[tid] * sq;
        bks[tid] = kb[tid] * sk + kbe[tid] - km[tid] * sk;
    }
    __syncthreads();

    // ---- projections + x*2 ----
    {
        const int i = tid;
        const long base = (long)b * CHW_ + (long)h * W_ + i;
        const float* xq = (d ? x_right : x_left) + base;
        const float* xk = (d ? x_left  : x_right) + base;

        {
            float xv[32];
            #pragma unroll
            for (int c = 0; c < 32; c++) xv[c] = xq[(long)c * HW_];
            float* ox = out + (d ? XN_ : 0) + base;
            #pragma unroll
            for (int c = 0; c < 32; c++) __stcs(ox + (long)c * HW_, 2.0f * xv[c]);
            ull x2[16];
            #pragma unroll
            for (int c2 = 0; c2 < 16; c2++) x2[c2] = pack2(xv[2*c2], xv[2*c2+1]);
            #pragma unroll
            for (int o = 0; o < 32; o++) {
                ull a0 = 0ull, a1 = 0ull;
                const ull* wr = (const ull*)(wqs + o * 32);
                #pragma unroll
                for (int c2 = 0; c2 < 16; c2 += 2) {
                    fma2(a0, wr[c2],   x2[c2]);
                    fma2(a1, wr[c2+1], x2[c2+1]);
                }
                qA[i * STR_ + o] = sum2(add2(a0, a1)) + bqs[o];
            }
        }
        {
            float xv[32];
            #pragma unroll
            for (int c = 0; c < 32; c++) xv[c] = xk[(long)c * HW_];
            ull x2[16];
            #pragma unroll
            for (int c2 = 0; c2 < 16; c2++) x2[c2] = pack2(xv[2*c2], xv[2*c2+1]);
            #pragma unroll
            for (int o = 0; o < 32; o++) {
                ull a0 = 0ull, a1 = 0ull;
                const ull* wr = (const ull*)(wks + o * 32);
                #pragma unroll
                for (int c2 = 0; c2 < 16; c2 += 2) {
                    fma2(a0, wr[c2],   x2[c2]);
                    fma2(a1, wr[c2+1], x2[c2+1]);
                }
                kA[i * STR_ + o] = sum2(add2(a0, a1)) + bks[o];
            }
        }
    }
    __syncthreads();   // qA/kA ready; wqs becomes band score staging

    const float* cbase = cost + (size_t)d * BHWW_ + (size_t)(b * H_ + h) * WW_;
    float*       obase = out  + (d ? (2*XN_ + BHWW_) : (2*XN_)) + (size_t)(b * H_ + h) * WW_;
    const int r0 = lane >> 3;           // 0..3
    const int c4 = (lane & 7) << 2;     // 0,4,...,28

    if (warp < 5) {
        // ================= streamer warps: ping-pong double buffer ==========
        const int n0 = COFF[warp], n1 = COFF[warp + 1];

        auto tile_cp = [&](int t) -> const float* {
            int code = CPTILE[t];
            int it = code >> 3, jt = code & 7;
            if (d) { const int tmp = it; it = jt; jt = tmp; }
            return cbase + (size_t)(it * 32) * W_ + (jt << 5);
        };
        auto tile_op = [&](int t) -> float* {
            int code = CPTILE[t];
            int it = code >> 3, jt = code & 7;
            if (d) { const int tmp = it; it = jt; jt = tmp; }
            return obase + (size_t)(it * 32) * W_ + (jt << 5);
        };

        float4 A[8], Bv[8];
        float* opA;
        float* opB;

        // prime A with first tile
        {
            const float* cp = tile_cp(n0);
            #pragma unroll
            for (int i = 0; i < 8; i++)
                A[i] = __ldcs((const float4*)(cp + (size_t)((i << 2) + r0) * W_ + c4));
            opA = tile_op(n0);
        }

        int t = n0;
        #pragma unroll 1
        while (t < n1) {
            // load next into B while A's stores go out
            if (t + 1 < n1) {
                const float* cp = tile_cp(t + 1);
                #pragma unroll
                for (int i = 0; i < 8; i++)
                    Bv[i] = __ldcs((const float4*)(cp + (size_t)((i << 2) + r0) * W_ + c4));
                opB = tile_op(t + 1);
            }
            #pragma unroll
            for (int i = 0; i < 8; i++)
                __stcs((float4*)(opA + (size_t)((i << 2) + r0) * W_ + c4), A[i]);
            t++;
            if (t >= n1) break;

            // load next into A while B's stores go out
            if (t + 1 < n1) {
                const float* cp = tile_cp(t + 1);
                #pragma unroll
                for (int i = 0; i < 8; i++)
                    A[i] = __ldcs((const float4*)(cp + (size_t)((i << 2) + r0) * W_ + c4));
                opA = tile_op(t + 1);
            }
            #pragma unroll
            for (int i = 0; i < 8; i++)
                __stcs((float4*)(opB + (size_t)((i << 2) + r0) * W_ + c4), Bv[i]);
            t++;
        }
    } else {
        // ================= band compute warps ==============================
        const int bw = warp - 5;
        const float inv_c = 1.0f / 32.0f;
        float* sw = wqs + (bw << 7);     // 128 floats per band warp

        #pragma unroll 1
        for (int t = BOFF[bw]; t < BOFF[bw + 1]; t++) {
            const int code = CTILE[t];
            int it = code >> 3, jt = code & 7;
            if (d) { const int tmp = it; it = jt; jt = tmp; }
            const float* cpt = cbase + (size_t)(it * 32) * W_ + (jt << 5);
            float*       opt = obase + (size_t)(it * 32) * W_ + (jt << 5);

            const int jj = (jt << 5) + lane;
            ull k2[16];
            {
                const ull* p = (const ull*)(kA + jj * STR_);
                #pragma unroll
                for (int u = 0; u < 16; u++) k2[u] = p[u];
            }
            float4 cur = __ldcs((const float4*)(cpt + (size_t)r0 * W_ + c4));

            #pragma unroll 1
            for (int cc = 0; cc < 8; cc++) {       // 4-row chunks
                const int row = (cc << 2) + r0;
                float4 nxt = cur;
                if (cc < 7)
                    nxt = __ldcs((const float4*)(cpt + (size_t)(row + 4) * W_ + c4));
                #pragma unroll
                for (int rr = 0; rr < 4; rr++) {
                    const int ii = (it << 5) + (cc << 2) + rr;
                    const ull* qrow = (const ull*)(qA + ii * STR_);
                    ull a0 = 0ull, a1 = 0ull;
                    #pragma unroll
                    for (int c2 = 0; c2 < 16; c2 += 2) {
                        fma2(a0, qrow[c2],   k2[c2]);
                        fma2(a1, qrow[c2+1], k2[c2+1]);
                    }
                    const float s = sum2(add2(a0, a1)) * inv_c;
                    const int df = d ? (jj - ii) : (ii - jj);
                    sw[(rr << 5) + ((((lane >> 2) ^ rr) & 7) << 2) + (lane & 3)] =
                        ((unsigned)df < (unsigned)CR_) ? s : 0.0f;
                }
                __syncwarp();
                const float4 s0 = *(const float4*)(sw + (r0 << 5) + ((((lane & 7) ^ r0) & 7) << 2));
                __syncwarp();
                float4 o4;
                o4.x = cur.x + s0.x; o4.y = cur.y + s0.y;
                o4.z = cur.z + s0.z; o4.w = cur.w + s0.w;
                __stcs((float4*)(opt + (size_t)row * W_ + c4), o4);
                cur = nxt;
            }
        }
    }
}

extern "C" void kernel_launch(void* const* d_in, const int* in_sizes, int n_in,
                              void* d_out, int out_size)
{
    (void)in_sizes; (void)n_in; (void)out_size;
    // qA/kA 69632 + weights/bias 8448 = 78080 bytes -> 2 CTAs/SM
    const int smem_bytes = 78080;
    cudaFuncSetAttribute(pab_kernel, cudaFuncAttributeMaxDynamicSharedMemorySize, smem_bytes);
    pab_kernel<<<2 * B_ * H_, 256, smem_bytes>>>(
        (const float*)d_in[0],  (const float*)d_in[1],  (const float*)d_in[2],
        (const float*)d_in[3],  (const float*)d_in[4],  (const float*)d_in[5],
        (const float*)d_in[6],  (const float*)d_in[7],  (const float*)d_in[8],
        (const float*)d_in[9],  (const float*)d_in[10], (const float*)d_in[11],
        (const float*)d_in[12], (const float*)d_in[13], (const float*)d_in[14],
        (float*)d_out);
}

// round 16
// speedup vs baseline: 1.5203x; 1.5203x over previous
#include <cuda_runtime.h>
#include <cuda_bf16.h>

#define B_    4
#define C_    32
#define H_    128
#define W_    256
#define CR_   85
#define HW_   (H_*W_)
#define CHW_  (C_*HW_)
#define WW_   (W_*W_)
#define BHWW_ (B_*H_*WW_)
#define XN_   (B_*CHW_)
#define RSTR_ 36            // row stride in u32 (144B): 16B aligned, 4-bank rotation

typedef unsigned int u32;
typedef unsigned long long ull;

// Per-warp interleaved schedule (R7): code = it*8+jt (d=0 frame), |0x80 = band tile.
__constant__ unsigned char SCHED[64] = {
       1,   128+0,     2,   128+9,     3,  128+18,     4,  128+27,
    128+36,     5,  128+45,     6,  128+54,     7,  128+63,    10,
      11,   128+8,    12,  128+17,    13,  128+26,    14,    15,
    128+35,    19,  128+44,    20,  128+53,    21,    22,    23,
      28,  128+62,    29,  128+16,    30,  128+25,    31,    32,
    128+34,    37,  128+43,    38,  128+52,    39,    40,    41,
      46,  128+61,    47,  128+24,    48,  128+33,    49,    50,
    128+42,    55,  128+51,    56,  128+60,    57,    58,    59
};

// ---- packed f32x2 helpers ----
__device__ __forceinline__ ull pack2(float lo, float hi) {
    ull r;
    asm("mov.b64 %0, {%1, %2};" : "=l"(r) : "f"(lo), "f"(hi));
    return r;
}
__device__ __forceinline__ void fma2(ull &d, ull a, ull b) {
    asm("fma.rn.f32x2 %0, %1, %2, %0;" : "+l"(d) : "l"(a), "l"(b));
}
__device__ __forceinline__ ull add2(ull a, ull b) {
    ull r;
    asm("add.rn.f32x2 %0, %1, %2;" : "=l"(r) : "l"(a), "l"(b));
    return r;
}
__device__ __forceinline__ float sum2(ull a) {
    float lo, hi;
    asm("mov.b64 {%0, %1}, %2;" : "=f"(lo), "=f"(hi) : "l"(a));
    return lo + hi;
}

// ---- tensor helpers (base ISA: ldmatrix + mma.sync bf16) ----
__device__ __forceinline__ u32 smem_u32(const void* p) {
    u32 a;
    asm("{ .reg .u64 t; cvta.to.shared.u64 t, %1; cvt.u32.u64 %0, t; }" : "=r"(a) : "l"(p));
    return a;
}
__device__ __forceinline__ void ldsm4(u32* r, u32 a) {
    asm volatile("ldmatrix.sync.aligned.m8n8.x4.shared.b16 {%0,%1,%2,%3}, [%4];"
        : "=r"(r[0]), "=r"(r[1]), "=r"(r[2]), "=r"(r[3]) : "r"(a));
}
__device__ __forceinline__ void mma16816(float* c, const u32* a, u32 b0, u32 b1) {
    asm volatile("mma.sync.aligned.m16n8k16.row.col.f32.bf16.bf16.f32 "
        "{%0,%1,%2,%3}, {%4,%5,%6,%7}, {%8,%9}, {%0,%1,%2,%3};"
        : "+f"(c[0]), "+f"(c[1]), "+f"(c[2]), "+f"(c[3])
        : "r"(a[0]), "r"(a[1]), "r"(a[2]), "r"(a[3]), "r"(b0), "r"(b1));
}
__device__ __forceinline__ u32 packbf2(float a, float b) {
    __nv_bfloat162 h;
    h.x = __float2bfloat16(a);
    h.y = __float2bfloat16(b);
    return *(u32*)&h;
}

extern "C" __global__ void __launch_bounds__(256, 2)
pab_kernel(const float* __restrict__ x_left, const float* __restrict__ x_right,
           const float* __restrict__ cost,
           const float* __restrict__ qw, const float* __restrict__ qb,
           const float* __restrict__ qg, const float* __restrict__ qbe,
           const float* __restrict__ qm, const float* __restrict__ qv,
           const float* __restrict__ kw, const float* __restrict__ kb,
           const float* __restrict__ kg, const float* __restrict__ kbe,
           const float* __restrict__ km, const float* __restrict__ kv,
           float* __restrict__ out)
{
    extern __shared__ u32 smu[];
    u32*   qS  = smu;                       // [256][36] u32: row = [qh x16u32 | ql x16u32 | pad]
    u32*   kS  = smu + 256 * RSTR_;         // [256][36]
    float* wqs = (float*)(smu + 2 * 256 * RSTR_);   // [1024]
    float* wks = wqs + 1024;                         // [1024]
    float* bqs = wks + 1024;                         // [32]
    float* bks = bqs + 32;                           // [32]

    const int tid  = threadIdx.x;
    const int warp = tid >> 5;
    const int lane = tid & 31;
    const int bx   = blockIdx.x;
    const int d    = bx & 1;
    const int bh   = bx >> 1;
    const int b    = bh >> 7;
    const int h    = bh & 127;

    // ---- fold BatchNorm into conv weights/bias (1/32 folded into k side) ----
    for (int t = tid; t < 1024; t += 256) {
        const int o = t >> 5;
        wqs[t] = qw[t] * (qg[o] * rsqrtf(qv[o] + 1e-5f));
        wks[t] = kw[t] * (kg[o] * rsqrtf(kv[o] + 1e-5f)) * 0.03125f;
    }
    if (tid < 32) {
        const float sq = qg[tid] * rsqrtf(qv[tid] + 1e-5f);
        const float sk = kg[tid] * rsqrtf(kv[tid] + 1e-5f);
        bqs[tid] = qb[tid] * sq + qbe[tid] - qm[tid] * sq;
        bks[tid] = (kb[tid] * sk + kbe[tid] - km[tid] * sk) * 0.03125f;
    }
    __syncthreads();

    // ---- projections + x*2; emit bf16 hi/lo rows ----
    {
        const long base = (long)b * CHW_ + (long)h * W_ + tid;
        // q side
        {
            const float* xq = (d ? x_right : x_left) + base;
            float xv[32];
            #pragma unroll
            for (int c = 0; c < 32; c++) xv[c] = xq[(long)c * HW_];
            float* ox = out + (d ? XN_ : 0) + base;
            #pragma unroll
            for (int c = 0; c < 32; c++) __stcs(ox + (long)c * HW_, 2.0f * xv[c]);
            ull x2[16];
            #pragma unroll
            for (int c2 = 0; c2 < 16; c2++) x2[c2] = pack2(xv[2*c2], xv[2*c2+1]);
            u32 hi2[16], lo2[16];
            #pragma unroll
            for (int o2 = 0; o2 < 16; o2++) {
                ull a0 = 0ull, a1 = 0ull, b0 = 0ull, b1 = 0ull;
                const ull* w0 = (const ull*)(wqs + (2*o2) * 32);
                const ull* w1 = (const ull*)(wqs + (2*o2+1) * 32);
                #pragma unroll
                for (int c2 = 0; c2 < 16; c2 += 2) {
                    fma2(a0, w0[c2],   x2[c2]);
                    fma2(a1, w0[c2+1], x2[c2+1]);
                    fma2(b0, w1[c2],   x2[c2]);
                    fma2(b1, w1[c2+1], x2[c2+1]);
                }
                const float s0 = sum2(add2(a0, a1)) + bqs[2*o2];
                const float s1 = sum2(add2(b0, b1)) + bqs[2*o2+1];
                const __nv_bfloat16 h0 = __float2bfloat16(s0);
                const __nv_bfloat16 h1 = __float2bfloat16(s1);
                __nv_bfloat162 hp; hp.x = h0; hp.y = h1;
                hi2[o2] = *(u32*)&hp;
                lo2[o2] = packbf2(s0 - __bfloat162float(h0), s1 - __bfloat162float(h1));
            }
            u32* row = qS + tid * RSTR_;
            #pragma unroll
            for (int i = 0; i < 4; i++) ((uint4*)row)[i] =
                make_uint4(hi2[4*i], hi2[4*i+1], hi2[4*i+2], hi2[4*i+3]);
            #pragma unroll
            for (int i = 0; i < 4; i++) ((uint4*)(row + 16))[i] =
                make_uint4(lo2[4*i], lo2[4*i+1], lo2[4*i+2], lo2[4*i+3]);
        }
        // k side
        {
            const float* xk = (d ? x_left : x_right) + base;
            float xv[32];
            #pragma unroll
            for (int c = 0; c < 32; c++) xv[c] = xk[(long)c * HW_];
            ull x2[16];
            #pragma unroll
            for (int c2 = 0; c2 < 16; c2++) x2[c2] = pack2(xv[2*c2], xv[2*c2+1]);
            u32 hi2[16], lo2[16];
            #pragma unroll
            for (int o2 = 0; o2 < 16; o2++) {
                ull a0 = 0ull, a1 = 0ull, b0 = 0ull, b1 = 0ull;
                const ull* w0 = (const ull*)(wks + (2*o2) * 32);
                const ull* w1 = (const ull*)(wks + (2*o2+1) * 32);
                #pragma unroll
                for (int c2 = 0; c2 < 16; c2 += 2) {
                    fma2(a0, w0[c2],   x2[c2]);
                    fma2(a1, w0[c2+1], x2[c2+1]);
                    fma2(b0, w1[c2],   x2[c2]);
                    fma2(b1, w1[c2+1], x2[c2+1]);
                }
                const float s0 = sum2(add2(a0, a1)) + bks[2*o2];
                const float s1 = sum2(add2(b0, b1)) + bks[2*o2+1];
                const __nv_bfloat16 h0 = __float2bfloat16(s0);
                const __nv_bfloat16 h1 = __float2bfloat16(s1);
                __nv_bfloat162 hp; hp.x = h0; hp.y = h1;
                hi2[o2] = *(u32*)&hp;
                lo2[o2] = packbf2(s0 - __bfloat162float(h0), s1 - __bfloat162float(h1));
            }
            u32* row = kS + tid * RSTR_;
            #pragma unroll
            for (int i = 0; i < 4; i++) ((uint4*)row)[i] =
                make_uint4(hi2[4*i], hi2[4*i+1], hi2[4*i+2], hi2[4*i+3]);
            #pragma unroll
            for (int i = 0; i < 4; i++) ((uint4*)(row + 16))[i] =
                make_uint4(lo2[4*i], lo2[4*i+1], lo2[4*i+2], lo2[4*i+3]);
        }
    }
    __syncthreads();

    // ---- sweep ----
    const float* cbase = cost + (size_t)d * BHWW_ + (size_t)(b * H_ + h) * WW_;
    float*       obase = out  + (d ? (2*XN_ + BHWW_) : (2*XN_)) + (size_t)(b * H_ + h) * WW_;
    const int r0 = lane >> 3, c4 = (lane & 7) << 2;
    const u32 smq = smem_u32(qS), smk = smem_u32(kS);

    #pragma unroll 1
    for (int n = 0; n < 8; n++) {
        const int e = SCHED[(warp << 3) + n];
        const int code = e & 63;
        int it = code >> 3, jt = code & 7;
        if (d) { const int tmp = it; it = jt; jt = tmp; }

        if (e & 128) {
            // ---- band tile via HMMA double-bf16 ----
            const int i0 = it << 5, j0 = jt << 5;
            // per-lane ldmatrix base: row (lane&15), col-half (lane>>4)
            const u32 qb = smq + (u32)((i0 + (lane & 15)) * 144 + (lane >> 4) * 16);
            const u32 kb = smk + (u32)((j0 + (lane & 15)) * 144 + (lane >> 4) * 16);

            float acc[2][4][4];
            #pragma unroll
            for (int mb = 0; mb < 2; mb++)
                #pragma unroll
                for (int nb = 0; nb < 4; nb++)
                    #pragma unroll
                    for (int u = 0; u < 4; u++) acc[mb][nb][u] = 0.0f;

            #pragma unroll
            for (int bhf = 0; bhf < 2; bhf++) {        // k half: hi, lo
                #pragma unroll
                for (int ks = 0; ks < 2; ks++) {        // k16 step within half
                    const u32 koff = (u32)(bhf * 64 + ks * 32);
                    u32 b0[4], b1[4];
                    ldsm4(b0, kb + koff);               // n0-15
                    ldsm4(b1, kb + 16 * 144 + koff);    // n16-31
                    #pragma unroll
                    for (int ahf = 0; ahf < 2; ahf++) { // q half: hi, lo
                        const u32 aoff = (u32)(ahf * 64 + ks * 32);
                        u32 a0[4], a1[4];
                        ldsm4(a0, qb + aoff);               // m0-15
                        ldsm4(a1, qb + 16 * 144 + aoff);    // m16-31
                        mma16816(acc[0][0], a0, b0[0], b0[2]);
                        mma16816(acc[0][1], a0, b0[1], b0[3]);
                        mma16816(acc[0][2], a0, b1[0], b1[2]);
                        mma16816(acc[0][3], a0, b1[1], b1[3]);
                        mma16816(acc[1][0], a1, b0[0], b0[2]);
                        mma16816(acc[1][1], a1, b0[1], b0[3]);
                        mma16816(acc[1][2], a1, b1[0], b1[2]);
                        mma16816(acc[1][3], a1, b1[1], b1[3]);
                    }
                }
            }

            // ---- epilogue: add cost directly in fragment layout ----
            #pragma unroll
            for (int mb = 0; mb < 2; mb++) {
                const int r = i0 + mb * 16 + (lane >> 2);
                #pragma unroll
                for (int nb = 0; nb < 4; nb++) {
                    const int cx = j0 + nb * 8 + ((lane & 3) << 1);
                    const float2 cv0 = __ldcs((const float2*)(cbase + (size_t)r * W_ + cx));
                    const float2 cv1 = __ldcs((const float2*)(cbase + (size_t)(r + 8) * W_ + cx));
                    const int dfa = d ? (cx - r) : (r - cx);
                    const int dfb = d ? (cx - r - 8) : (r + 8 - cx);
                    float2 o0, o1;
                    o0.x = cv0.x + (((unsigned)dfa       < (unsigned)CR_) ? acc[mb][nb][0] : 0.0f);
                    o0.y = cv0.y + (((unsigned)(d ? dfa+1 : dfa-1) < (unsigned)CR_) ? acc[mb][nb][1] : 0.0f);
                    o1.x = cv1.x + (((unsigned)dfb       < (unsigned)CR_) ? acc[mb][nb][2] : 0.0f);
                    o1.y = cv1.y + (((unsigned)(d ? dfb+1 : dfb-1) < (unsigned)CR_) ? acc[mb][nb][3] : 0.0f);
                    __stcs((float2*)(obase + (size_t)r * W_ + cx), o0);
                    __stcs((float2*)(obase + (size_t)(r + 8) * W_ + cx), o1);
                }
            }
        } else {
            // ---- pure copy tile ----
            const float* cpt = cbase + (size_t)(it * 32) * W_ + (jt << 5);
            float*       opt = obase + (size_t)(it * 32) * W_ + (jt << 5);
            float4 v[8];
            #pragma unroll
            for (int t = 0; t < 8; t++)
                v[t] = __ldcs((const float4*)(cpt + (size_t)((t << 2) + r0) * W_ + c4));
            #pragma unroll
            for (int t = 0; t < 8; t++)
                __stcs((float4*)(opt + (size_t)((t << 2) + r0) * W_ + c4), v[t]);
        }
    }
}

extern "C" void kernel_launch(void* const* d_in, const int* in_sizes, int n_in,
                              void* d_out, int out_size)
{
    (void)in_sizes; (void)n_in; (void)out_size;
    // qS/kS 73728 + weights 8192 + bias 256 = 82176 bytes -> 2 CTAs/SM
    const int smem_bytes = 82176;
    cudaFuncSetAttribute(pab_kernel, cudaFuncAttributeMaxDynamicSharedMemorySize, smem_bytes);
    pab_kernel<<<2 * B_ * H_, 256, smem_bytes>>>(
        (const float*)d_in[0],  (const float*)d_in[1],  (const float*)d_in[2],
        (const float*)d_in[3],  (const float*)d_in[4],  (const float*)d_in[5],
        (const float*)d_in[6],  (const float*)d_in[7],  (const float*)d_in[8],
        (const float*)d_in[9],  (const float*)d_in[10], (const float*)d_in[11],
        (const float*)d_in[12], (const float*)d_in[13], (const float*)d_in[14],
        (float*)d_out);
}

// round 17
// speedup vs baseline: 1.6803x; 1.1052x over previous
#include <cuda_runtime.h>
#include <cuda_bf16.h>

#define B_    4
#define C_    32
#define H_    128
#define W_    256
#define CR_   85
#define HW_   (H_*W_)
#define CHW_  (C_*HW_)
#define WW_   (W_*W_)
#define BHWW_ (B_*H_*WW_)
#define XN_   (B_*CHW_)
#define NCOMP 1024
#define NCOPY 2432

typedef unsigned int u32;
typedef unsigned long long ull;

// band tiles (d=0 frame: it-jt in [0,3]); copy tiles = the rest
__constant__ unsigned char CTILE[26] = {
    0, 9, 18, 27, 36, 45, 54, 63,
    8, 17, 26, 35, 44, 53, 62,
    16, 25, 34, 43, 52, 61,
    24, 33, 42, 51, 60
};
__constant__ unsigned char CPTILE[38] = {
    1, 2, 3, 4, 5, 6, 7,
    10, 11, 12, 13, 14, 15,
    19, 20, 21, 22, 23,
    28, 29, 30, 31,
    32, 37, 38, 39,
    40, 41, 46, 47,
    48, 49, 50, 55,
    56, 57, 58, 59
};

// ---- packed f32x2 helpers ----
__device__ __forceinline__ ull pack2(float lo, float hi) {
    ull r;
    asm("mov.b64 %0, {%1, %2};" : "=l"(r) : "f"(lo), "f"(hi));
    return r;
}
__device__ __forceinline__ void fma2(ull &d, ull a, ull b) {
    asm("fma.rn.f32x2 %0, %1, %2, %0;" : "+l"(d) : "l"(a), "l"(b));
}
__device__ __forceinline__ ull add2(ull a, ull b) {
    ull r;
    asm("add.rn.f32x2 %0, %1, %2;" : "=l"(r) : "l"(a), "l"(b));
    return r;
}
__device__ __forceinline__ float sum2(ull a) {
    float lo, hi;
    asm("mov.b64 {%0, %1}, %2;" : "=f"(lo), "=f"(hi) : "l"(a));
    return lo + hi;
}

// ---- tensor helpers (base ISA: ldmatrix + mma.sync bf16) ----
__device__ __forceinline__ u32 smem_u32(const void* p) {
    u32 a;
    asm("{ .reg .u64 t; cvta.to.shared.u64 t, %1; cvt.u32.u64 %0, t; }" : "=r"(a) : "l"(p));
    return a;
}
__device__ __forceinline__ void ldsm4(u32* r, u32 a) {
    asm volatile("ldmatrix.sync.aligned.m8n8.x4.shared.b16 {%0,%1,%2,%3}, [%4];"
        : "=r"(r[0]), "=r"(r[1]), "=r"(r[2]), "=r"(r[3]) : "r"(a));
}
__device__ __forceinline__ void mma16816(float* c, const u32* a, u32 b0, u32 b1) {
    asm volatile("mma.sync.aligned.m16n8k16.row.col.f32.bf16.bf16.f32 "
        "{%0,%1,%2,%3}, {%4,%5,%6,%7}, {%8,%9}, {%0,%1,%2,%3};"
        : "+f"(c[0]), "+f"(c[1]), "+f"(c[2]), "+f"(c[3])
        : "r"(a[0]), "r"(a[1]), "r"(a[2]), "r"(a[3]), "r"(b0), "r"(b1));
}
__device__ __forceinline__ u32 packbf2(float a, float b) {
    __nv_bfloat162 h;
    h.x = __float2bfloat16(a);
    h.y = __float2bfloat16(b);
    return *(u32*)&h;
}

extern "C" __global__ void __launch_bounds__(256, 2)
pab_kernel(const float* __restrict__ x_left, const float* __restrict__ x_right,
           const float* __restrict__ cost,
           const float* __restrict__ qw, const float* __restrict__ qb,
           const float* __restrict__ qg, const float* __restrict__ qbe,
           const float* __restrict__ qm, const float* __restrict__ qv,
           const float* __restrict__ kw, const float* __restrict__ kb,
           const float* __restrict__ kg, const float* __restrict__ kbe,
           const float* __restrict__ km, const float* __restrict__ kv,
           float* __restrict__ out)
{
    const int tid  = threadIdx.x;
    const int warp = tid >> 5;
    const int lane = tid & 31;
    const int bx   = blockIdx.x;
    const int r0 = lane >> 3, c4 = (lane & 7) << 2;

    if (bx >= NCOMP) {
        // ================== pure-copy streamer block ==================
        // 2 tiles per warp: both tile's loads in flight before stores
        const int w2 = (bx - NCOMP) * 16 + warp * 2;
        #pragma unroll
        for (int half = 0; half < 1; half++) {}   // (no-op; keeps structure flat)
        int dbh0 = w2 / 38,       tt0 = w2 - dbh0 * 38;
        int dbh1 = (w2+1) / 38,   tt1 = (w2+1) - dbh1 * 38;

        const float* cp[2];
        float*       op[2];
        {
            int code = CPTILE[tt0];
            int it = code >> 3, jt = code & 7;
            if (dbh0 & 1) { int tmp = it; it = jt; jt = tmp; }
            size_t off = (size_t)(dbh0 & 1) * BHWW_ + (size_t)(dbh0 >> 1) * WW_
                       + (size_t)(it * 32) * W_ + (jt << 5);
            cp[0] = cost + off;
            op[0] = out + 2 * (size_t)XN_ + off;
        }
        {
            int code = CPTILE[tt1];
            int it = code >> 3, jt = code & 7;
            if (dbh1 & 1) { int tmp = it; it = jt; jt = tmp; }
            size_t off = (size_t)(dbh1 & 1) * BHWW_ + (size_t)(dbh1 >> 1) * WW_
                       + (size_t)(it * 32) * W_ + (jt << 5);
            cp[1] = cost + off;
            op[1] = out + 2 * (size_t)XN_ + off;
        }

        float4 v[16];
        #pragma unroll
        for (int p = 0; p < 2; p++)
            #pragma unroll
            for (int t = 0; t < 8; t++)
                v[p * 8 + t] = __ldcs((const float4*)(cp[p] + (size_t)((t << 2) + r0) * W_ + c4));
        #pragma unroll
        for (int p = 0; p < 2; p++)
            #pragma unroll
            for (int t = 0; t < 8; t++)
                __stcs((float4*)(op[p] + (size_t)((t << 2) + r0) * W_ + c4), v[p * 8 + t]);
        return;
    }

    // ================== compute block: proj + band tiles ==================
    extern __shared__ u32 smu[];
    u32*   qS  = smu;                       // [256][36] u32: [qh x16 | ql x16 | pad]
    u32*   kS  = smu + 256 * 36;
    float* wqs = (float*)(smu + 2 * 256 * 36);
    float* wks = wqs + 1024;
    float* bqs = wks + 1024;
    float* bks = bqs + 32;

    const int d  = bx & 1;
    const int bh = bx >> 1;
    const int b  = bh >> 7;
    const int h  = bh & 127;

    for (int t = tid; t < 1024; t += 256) {
        const int o = t >> 5;
        wqs[t] = qw[t] * (qg[o] * rsqrtf(qv[o] + 1e-5f));
        wks[t] = kw[t] * (kg[o] * rsqrtf(kv[o] + 1e-5f)) * 0.03125f;
    }
    if (tid < 32) {
        const float sq = qg[tid] * rsqrtf(qv[tid] + 1e-5f);
        const float sk = kg[tid] * rsqrtf(kv[tid] + 1e-5f);
        bqs[tid] = qb[tid] * sq + qbe[tid] - qm[tid] * sq;
        bks[tid] = (kb[tid] * sk + kbe[tid] - km[tid] * sk) * 0.03125f;
    }
    __syncthreads();

    // ---- projections + x*2; emit bf16 hi/lo rows ----
    {
        const long base = (long)b * CHW_ + (long)h * W_ + tid;
        // q side
        {
            const float* xq = (d ? x_right : x_left) + base;
            float xv[32];
            #pragma unroll
            for (int c = 0; c < 32; c++) xv[c] = xq[(long)c * HW_];
            float* ox = out + (d ? XN_ : 0) + base;
            #pragma unroll
            for (int c = 0; c < 32; c++) __stcs(ox + (long)c * HW_, 2.0f * xv[c]);
            ull x2[16];
            #pragma unroll
            for (int c2 = 0; c2 < 16; c2++) x2[c2] = pack2(xv[2*c2], xv[2*c2+1]);
            u32 hi2[16], lo2[16];
            #pragma unroll
            for (int o2 = 0; o2 < 16; o2++) {
                ull a0 = 0ull, a1 = 0ull, b0 = 0ull, b1 = 0ull;
                const ull* w0 = (const ull*)(wqs + (2*o2) * 32);
                const ull* w1 = (const ull*)(wqs + (2*o2+1) * 32);
                #pragma unroll
                for (int c2 = 0; c2 < 16; c2 += 2) {
                    fma2(a0, w0[c2],   x2[c2]);
                    fma2(a1, w0[c2+1], x2[c2+1]);
                    fma2(b0, w1[c2],   x2[c2]);
                    fma2(b1, w1[c2+1], x2[c2+1]);
                }
                const float s0 = sum2(add2(a0, a1)) + bqs[2*o2];
                const float s1 = sum2(add2(b0, b1)) + bqs[2*o2+1];
                const __nv_bfloat16 h0 = __float2bfloat16(s0);
                const __nv_bfloat16 h1 = __float2bfloat16(s1);
                __nv_bfloat162 hp; hp.x = h0; hp.y = h1;
                hi2[o2] = *(u32*)&hp;
                lo2[o2] = packbf2(s0 - __bfloat162float(h0), s1 - __bfloat162float(h1));
            }
            u32* row = qS + tid * 36;
            #pragma unroll
            for (int i = 0; i < 4; i++) ((uint4*)row)[i] =
                make_uint4(hi2[4*i], hi2[4*i+1], hi2[4*i+2], hi2[4*i+3]);
            #pragma unroll
            for (int i = 0; i < 4; i++) ((uint4*)(row + 16))[i] =
                make_uint4(lo2[4*i], lo2[4*i+1], lo2[4*i+2], lo2[4*i+3]);
        }
        // k side
        {
            const float* xk = (d ? x_left : x_right) + base;
            float xv[32];
            #pragma unroll
            for (int c = 0; c < 32; c++) xv[c] = xk[(long)c * HW_];
            ull x2[16];
            #pragma unroll
            for (int c2 = 0; c2 < 16; c2++) x2[c2] = pack2(xv[2*c2], xv[2*c2+1]);
            u32 hi2[16], lo2[16];
            #pragma unroll
            for (int o2 = 0; o2 < 16; o2++) {
                ull a0 = 0ull, a1 = 0ull, b0 = 0ull, b1 = 0ull;
                const ull* w0 = (const ull*)(wks + (2*o2) * 32);
                const ull* w1 = (const ull*)(wks + (2*o2+1) * 32);
                #pragma unroll
                for (int c2 = 0; c2 < 16; c2 += 2) {
                    fma2(a0, w0[c2],   x2[c2]);
                    fma2(a1, w0[c2+1], x2[c2+1]);
                    fma2(b0, w1[c2],   x2[c2]);
                    fma2(b1, w1[c2+1], x2[c2+1]);
                }
                const float s0 = sum2(add2(a0, a1)) + bks[2*o2];
                const float s1 = sum2(add2(b0, b1)) + bks[2*o2+1];
                const __nv_bfloat16 h0 = __float2bfloat16(s0);
                const __nv_bfloat16 h1 = __float2bfloat16(s1);
                __nv_bfloat162 hp; hp.x = h0; hp.y = h1;
                hi2[o2] = *(u32*)&hp;
                lo2[o2] = packbf2(s0 - __bfloat162float(h0), s1 - __bfloat162float(h1));
            }
            u32* row = kS + tid * 36;
            #pragma unroll
            for (int i = 0; i < 4; i++) ((uint4*)row)[i] =
                make_uint4(hi2[4*i], hi2[4*i+1], hi2[4*i+2], hi2[4*i+3]);
            #pragma unroll
            for (int i = 0; i < 4; i++) ((uint4*)(row + 16))[i] =
                make_uint4(lo2[4*i], lo2[4*i+1], lo2[4*i+2], lo2[4*i+3]);
        }
    }
    __syncthreads();

    // ---- band tiles via HMMA double-bf16 ----
    const float* cbase = cost + (size_t)d * BHWW_ + (size_t)(b * H_ + h) * WW_;
    float*       obase = out  + (d ? (2*XN_ + BHWW_) : (2*XN_)) + (size_t)(b * H_ + h) * WW_;
    const u32 smq = smem_u32(qS), smk = smem_u32(kS);

    #pragma unroll 1
    for (int t = warp; t < 26; t += 8) {
        const int code = CTILE[t];
        int it = code >> 3, jt = code & 7;
        if (d) { const int tmp = it; it = jt; jt = tmp; }
        const int i0 = it << 5, j0 = jt << 5;
        const u32 qb_ = smq + (u32)((i0 + (lane & 15)) * 144 + (lane >> 4) * 16);
        const u32 kb_ = smk + (u32)((j0 + (lane & 15)) * 144 + (lane >> 4) * 16);

        float acc[2][4][4];
        #pragma unroll
        for (int mb = 0; mb < 2; mb++)
            #pragma unroll
            for (int nb = 0; nb < 4; nb++)
                #pragma unroll
                for (int u = 0; u < 4; u++) acc[mb][nb][u] = 0.0f;

        #pragma unroll
        for (int bhf = 0; bhf < 2; bhf++) {
            #pragma unroll
            for (int ks = 0; ks < 2; ks++) {
                const u32 koff = (u32)(bhf * 64 + ks * 32);
                u32 b0[4], b1[4];
                ldsm4(b0, kb_ + koff);
                ldsm4(b1, kb_ + 16 * 144 + koff);
                #pragma unroll
                for (int ahf = 0; ahf < 2; ahf++) {
                    const u32 aoff = (u32)(ahf * 64 + ks * 32);
                    u32 a0[4], a1[4];
                    ldsm4(a0, qb_ + aoff);
                    ldsm4(a1, qb_ + 16 * 144 + aoff);
                    mma16816(acc[0][0], a0, b0[0], b0[2]);
                    mma16816(acc[0][1], a0, b0[1], b0[3]);
                    mma16816(acc[0][2], a0, b1[0], b1[2]);
                    mma16816(acc[0][3], a0, b1[1], b1[3]);
                    mma16816(acc[1][0], a1, b0[0], b0[2]);
                    mma16816(acc[1][1], a1, b0[1], b0[3]);
                    mma16816(acc[1][2], a1, b1[0], b1[2]);
                    mma16816(acc[1][3], a1, b1[1], b1[3]);
                }
            }
        }

        #pragma unroll
        for (int mb = 0; mb < 2; mb++) {
            const int r = i0 + mb * 16 + (lane >> 2);
            #pragma unroll
            for (int nb = 0; nb < 4; nb++) {
                const int cx = j0 + nb * 8 + ((lane & 3) << 1);
                const float2 cv0 = __ldcs((const float2*)(cbase + (size_t)r * W_ + cx));
                const float2 cv1 = __ldcs((const float2*)(cbase + (size_t)(r + 8) * W_ + cx));
                const int dfa = d ? (cx - r) : (r - cx);
                const int dfb = d ? (cx - r - 8) : (r + 8 - cx);
                float2 o0, o1;
                o0.x = cv0.x + (((unsigned)dfa < (unsigned)CR_) ? acc[mb][nb][0] : 0.0f);
                o0.y = cv0.y + (((unsigned)(d ? dfa+1 : dfa-1) < (unsigned)CR_) ? acc[mb][nb][1] : 0.0f);
                o1.x = cv1.x + (((unsigned)dfb < (unsigned)CR_) ? acc[mb][nb][2] : 0.0f);
                o1.y = cv1.y + (((unsigned)(d ? dfb+1 : dfb-1) < (unsigned)CR_) ? acc[mb][nb][3] : 0.0f);
                __stcs((float2*)(obase + (size_t)r * W_ + cx), o0);
                __stcs((float2*)(obase + (size_t)(r + 8) * W_ + cx), o1);
            }
        }
    }
}

extern "C" void kernel_launch(void* const* d_in, const int* in_sizes, int n_in,
                              void* d_out, int out_size)
{
    (void)in_sizes; (void)n_in; (void)out_size;
    // qS/kS 73728 + weights 8192 + bias 256 = 82176 bytes -> 2 CTAs/SM
    const int smem_bytes = 82176;
    cudaFuncSetAttribute(pab_kernel, cudaFuncAttributeMaxDynamicSharedMemorySize, smem_bytes);
    pab_kernel<<<NCOMP + NCOPY, 256, smem_bytes>>>(
        (const float*)d_in[0],  (const float*)d_in[1],  (const float*)d_in[2],
        (const float*)d_in[3],  (const float*)d_in[4],  (const float*)d_in[5],
        (const float*)d_in[6],  (const float*)d_in[7],  (const float*)d_in[8],
        (const float*)d_in[9],  (const float*)d_in[10], (const float*)d_in[11],
        (const float*)d_in[12], (const float*)d_in[13], (const float*)d_in[14],
        (float*)d_out);
}